// round 16
// baseline (speedup 1.0000x reference)
#include <cuda_runtime.h>
#include <cuda_fp16.h>
#include <cstdint>

#define N_NODES_MAX 100000
#define N_EDGES_MAX 1600000

// ---------------- device scratch (no allocations allowed) ----------------
__device__ __half g_hA[(size_t)N_NODES_MAX * 128];  // GEMM output ping
__device__ __half g_hB[(size_t)N_NODES_MAX * 128];  // GEMM output pong
__device__ __half g_y[(size_t)N_NODES_MAX * 128];   // agg output (fp16, GEMM A)
__device__ float g_dinv[N_NODES_MAX];
__device__ int   g_count[N_NODES_MAX];
__device__ int   g_fill[N_NODES_MAX];
__device__ int   g_rowptr[N_NODES_MAX + 1];
__device__ uint2 g_epk[N_EDGES_MAX];                // packed (src, norm-bits)
__device__ int   g_bsums[256];
__device__ int   g_is32;
// transposed fp16 weights: WT[n][k]
__device__ __half g_wt1[128 * 384];
__device__ __half g_wt2[128 * 128];
__device__ __half g_wt3[128 * 128];
__device__ __half g_wt4[128 * 128];
__device__ __half g_wt5[64 * 128];

// ---------------- helpers ----------------
__device__ __forceinline__ int edge_val(const void* ei, int is32, long long idx) {
    if (is32) return ((const int*)ei)[idx];
    return (int)((const long long*)ei)[idx];
}
__device__ __forceinline__ void cp_async16(uint32_t dst, const void* src, int srcsize) {
    asm volatile("cp.async.ca.shared.global [%0], [%1], 16, %2;"
                 :: "r"(dst), "l"(src), "r"(srcsize));
}
__device__ __forceinline__ void cp_commit() { asm volatile("cp.async.commit_group;"); }
template<int N>
__device__ __forceinline__ void cp_wait() { asm volatile("cp.async.wait_group %0;" :: "n"(N)); }

__device__ __forceinline__ void ldsm_x4(uint32_t& r0, uint32_t& r1, uint32_t& r2, uint32_t& r3,
                                        uint32_t addr) {
    asm volatile("ldmatrix.sync.aligned.m8n8.x4.shared.b16 {%0,%1,%2,%3}, [%4];"
                 : "=r"(r0), "=r"(r1), "=r"(r2), "=r"(r3) : "r"(addr));
}

// ---------------- preprocessing kernels ----------------
__global__ void k_init(const void* ei, int E, long long N, int n) {
    int i = blockIdx.x * blockDim.x + threadIdx.x;
    if (i < n) g_count[i] = 0;
    if (i == 0) {
        const long long* p = (const long long*)ei;
        int is32 = 0;
        for (int j = 0; j < 64 && j < E; j++) {
            long long v = p[j];
            if (v < 0 || v >= N) { is32 = 1; break; }
        }
        g_is32 = is32;
    }
}

// histogram over dst; 2 edges per thread with vector loads
__global__ void k_hist(const void* __restrict__ ei, int E) {
    int i = blockIdx.x * blockDim.x + threadIdx.x;
    int e = i * 2;
    if (e >= E) return;
    int is32 = g_is32;
    int d0, d1 = -1;
    bool pair = (e + 1 < E) && ((E & 1) == 0);
    if (pair) {
        if (is32) {
            int2 v = *(const int2*)((const int*)ei + (size_t)E + e);
            d0 = v.x; d1 = v.y;
        } else {
            longlong2 v = *(const longlong2*)((const long long*)ei + (size_t)E + e);
            d0 = (int)v.x; d1 = (int)v.y;
        }
    } else {
        d0 = edge_val(ei, is32, (long long)E + e);
        if (e + 1 < E) d1 = edge_val(ei, is32, (long long)E + e + 1);
    }
    atomicAdd(&g_count[d0], 1);
    if (d1 >= 0) atomicAdd(&g_count[d1], 1);
}

// scan over counts; also computes dinv (fused)
__global__ void k_scan1(int n) {
    __shared__ int s[1024];
    int t = threadIdx.x;
    int i = blockIdx.x * 1024 + t;
    int v = (i < n) ? g_count[i] : 0;
    if (i < n) g_dinv[i] = rsqrtf((float)v + 1.0f);
    s[t] = v;
    __syncthreads();
    #pragma unroll
    for (int off = 1; off < 1024; off <<= 1) {
        int x = (t >= off) ? s[t - off] : 0;
        __syncthreads();
        s[t] += x;
        __syncthreads();
    }
    if (i < n) g_rowptr[i] = s[t] - v;
    if (t == 1023) g_bsums[blockIdx.x] = s[1023];
}

// parallel block-sum scan (256 threads; nb <= 256)
__global__ void k_scan2(int nb, int n) {
    __shared__ int s[256];
    int t = threadIdx.x;
    int v = (t < nb) ? g_bsums[t] : 0;
    s[t] = v;
    __syncthreads();
    #pragma unroll
    for (int off = 1; off < 256; off <<= 1) {
        int x = (t >= off) ? s[t - off] : 0;
        __syncthreads();
        s[t] += x;
        __syncthreads();
    }
    if (t < nb) g_bsums[t] = s[t] - v;   // exclusive block offsets
    if (t == 255) g_rowptr[n] = s[255];
}

// add block offsets; also zero g_fill (needed before scatter)
__global__ void k_scan3(int n) {
    int i = blockIdx.x * blockDim.x + threadIdx.x;
    if (i < n) {
        g_rowptr[i] += g_bsums[i >> 10];
        g_fill[i] = 0;
    }
}

// scatter edges into CSR; 2 edges per thread with vector loads
__global__ void k_scatter(const void* __restrict__ ei, int E) {
    int i = blockIdx.x * blockDim.x + threadIdx.x;
    int e = i * 2;
    if (e >= E) return;
    int is32 = g_is32;
    int s0, d0, s1 = -1, d1 = -1;
    bool pair = (e + 1 < E) && ((E & 1) == 0);
    if (pair) {
        if (is32) {
            int2 vs = *(const int2*)((const int*)ei + e);
            int2 vd = *(const int2*)((const int*)ei + (size_t)E + e);
            s0 = vs.x; s1 = vs.y; d0 = vd.x; d1 = vd.y;
        } else {
            longlong2 vs = *(const longlong2*)((const long long*)ei + e);
            longlong2 vd = *(const longlong2*)((const long long*)ei + (size_t)E + e);
            s0 = (int)vs.x; s1 = (int)vs.y; d0 = (int)vd.x; d1 = (int)vd.y;
        }
    } else {
        s0 = edge_val(ei, is32, e);
        d0 = edge_val(ei, is32, (long long)E + e);
        if (e + 1 < E) {
            s1 = edge_val(ei, is32, e + 1);
            d1 = edge_val(ei, is32, (long long)E + e + 1);
        }
    }
    {
        int pos = g_rowptr[d0] + atomicAdd(&g_fill[d0], 1);
        g_epk[pos] = make_uint2((unsigned)s0, __float_as_uint(g_dinv[s0] * g_dinv[d0]));
    }
    if (s1 >= 0) {
        int pos = g_rowptr[d1] + atomicAdd(&g_fill[d1], 1);
        g_epk[pos] = make_uint2((unsigned)s1, __float_as_uint(g_dinv[s1] * g_dinv[d1]));
    }
}

// ---------------- weight transposes (fp16) ----------------
__global__ void k_wtrans1(const float* __restrict__ W1) {
    int idx = blockIdx.x * 256 + threadIdx.x;
    if (idx < 49152) {
        int n = idx / 384, k = idx % 384;
        g_wt1[idx] = __float2half_rn(W1[(size_t)k * 128 + n]);
    }
}
__global__ void k_wtrans_rest(const float* __restrict__ W2, const float* __restrict__ W3,
                              const float* __restrict__ W4, const float* __restrict__ W5) {
    int idx = blockIdx.x * 256 + threadIdx.x;
    if (idx < 16384) {
        int n = idx / 128, k = idx % 128;
        g_wt2[idx] = __float2half_rn(W2[(size_t)k * 128 + n]);
    } else if (idx < 32768) {
        int j = idx - 16384; int n = j / 128, k = j % 128;
        g_wt3[j] = __float2half_rn(W3[(size_t)k * 128 + n]);
    } else if (idx < 49152) {
        int j = idx - 32768; int n = j / 128, k = j % 128;
        g_wt4[j] = __float2half_rn(W4[(size_t)k * 128 + n]);
    } else if (idx < 49152 + 8192) {
        int j = idx - 49152; int n = j / 128, k = j % 128;
        g_wt5[j] = (n < 50) ? __float2half_rn(W5[(size_t)k * 50 + n]) : __float2half_rn(0.f);
    }
}

// ---------------- GEMM1: fp32 A (fused cvt), 2-stage smem ----------
template<int KT, int BN, int SC>
__global__ __launch_bounds__(256, 2) void k_gemm_cvt(const float* __restrict__ A32,
                                                     const __half* __restrict__ WT,
                                                     __half* __restrict__ C, int M) {
    constexpr int BM = 128, BKH = 32;
    constexpr int WTN = BN / 4;
    constexpr int NTL = WTN / 8;
    constexpr int LDR = BKH + 8;            // 40 halves = 80B rows
    constexpr int NK  = KT / BKH;
    constexpr int AST = BM * LDR;
    constexpr int WST = BN * LDR;
    constexpr int WCH = BN * 4 / 256;

    extern __shared__ __half smem[];
    __half* Abase = smem;                    // 2 stages
    __half* Wbase = smem + 2 * AST;

    const int tid = threadIdx.x;
    const int wid = tid >> 5;
    const int lane = tid & 31;
    const int g = lane >> 2;
    const int t = lane & 3;
    const int warp_m = wid >> 2;
    const int warp_n = wid & 3;
    const int row0 = blockIdx.x * BM;

    const uint32_t sA = (uint32_t)__cvta_generic_to_shared(Abase);
    const uint32_t sW = (uint32_t)__cvta_generic_to_shared(Wbase);

    float acc[4][NTL][4];
    #pragma unroll
    for (int i = 0; i < 4; i++)
        #pragma unroll
        for (int j = 0; j < NTL; j++)
            #pragma unroll
            for (int r = 0; r < 4; r++) acc[i][j][r] = 0.f;

    float4 pa[4];

    auto cpW = [&](int i, int st) {
        const int kb = i * BKH;
        #pragma unroll
        for (int j = 0; j < WCH; j++) {
            int idx = tid + j * 256;
            int n = idx >> 2, ch = idx & 3;
            cp_async16(sW + (uint32_t)((st * WST + n * LDR + ch * 8) * 2),
                       WT + (size_t)n * KT + kb + ch * 8, 16);
        }
    };
    auto ldA = [&](int i) {
        const int kb = i * BKH;
        #pragma unroll
        for (int j = 0; j < 4; j++) {
            int idx = tid + j * 256;
            int r = idx >> 3, c4 = idx & 7;
            int grow = row0 + r;
            pa[j] = (grow < M)
                ? __ldg((const float4*)(A32 + (size_t)grow * KT + kb + c4 * 4))
                : make_float4(0.f, 0.f, 0.f, 0.f);
        }
    };
    auto stsA = [&](int st) {
        #pragma unroll
        for (int j = 0; j < 4; j++) {
            int idx = tid + j * 256;
            int r = idx >> 3, c4 = idx & 7;
            __half2 h0 = __floats2half2_rn(pa[j].x, pa[j].y);
            __half2 h1 = __floats2half2_rn(pa[j].z, pa[j].w);
            uint2 u;
            u.x = *(uint32_t*)&h0;
            u.y = *(uint32_t*)&h1;
            *(uint2*)(Abase + st * AST + r * LDR + c4 * 4) = u;
        }
    };
    auto compute = [&](int st) {
        #pragma unroll
        for (int ks = 0; ks < 2; ks++) {
            const int k16 = ks * 16;
            uint32_t bf[NTL][2];
            #pragma unroll
            for (int np = 0; np < NTL / 2; np++) {
                int n0 = warp_n * WTN + np * 16;
                uint32_t ad = sW + (uint32_t)(((st * WST) +
                              (n0 + (lane & 7) + ((lane >> 4) & 1) * 8) * LDR +
                              k16 + ((lane >> 3) & 1) * 8) * 2);
                ldsm_x4(bf[2 * np][0], bf[2 * np][1], bf[2 * np + 1][0], bf[2 * np + 1][1], ad);
            }
            #pragma unroll
            for (int mt = 0; mt < 4; mt++) {
                int mb = warp_m * 64 + mt * 16;
                uint32_t ad = sA + (uint32_t)(((st * AST) +
                              (mb + (lane & 15)) * LDR + k16 + (lane >> 4) * 8) * 2);
                uint32_t a0, a1, a2, a3;
                ldsm_x4(a0, a1, a2, a3, ad);
                #pragma unroll
                for (int nt = 0; nt < NTL; nt++) {
                    asm volatile(
                        "mma.sync.aligned.m16n8k16.row.col.f32.f16.f16.f32 "
                        "{%0,%1,%2,%3}, {%4,%5,%6,%7}, {%8,%9}, {%0,%1,%2,%3};"
                        : "+f"(acc[mt][nt][0]), "+f"(acc[mt][nt][1]),
                          "+f"(acc[mt][nt][2]), "+f"(acc[mt][nt][3])
                        : "r"(a0), "r"(a1), "r"(a2), "r"(a3),
                          "r"(bf[nt][0]), "r"(bf[nt][1]));
                }
            }
        }
    };

    ldA(0);
    cpW(0, 0); cp_commit();
    stsA(0);
    ldA(1);
    cpW(1, 1); cp_commit();
    cp_wait<1>();
    __syncthreads();

    for (int i = 0; i < NK; i++) {
        const int st = i & 1;
        compute(st);
        __syncthreads();
        if (i + 1 < NK) stsA((i + 1) & 1);
        if (i + 2 < NK) { ldA(i + 2); cpW(i + 2, st); }
        cp_commit();
        cp_wait<1>();
        __syncthreads();
    }

    // ---- epilogue: stage C in smem, coalesced STG.128 ----
    __syncthreads();
    constexpr int CLDR = BN + 8;
    __half* Cs = smem;
    #pragma unroll
    for (int mt = 0; mt < 4; mt++) {
        int rl = warp_m * 64 + mt * 16 + g;
        #pragma unroll
        for (int nt = 0; nt < NTL; nt++) {
            int col = warp_n * WTN + nt * 8 + t * 2;
            *(__half2*)(Cs + rl * CLDR + col) =
                __floats2half2_rn(acc[mt][nt][0], acc[mt][nt][1]);
            *(__half2*)(Cs + (rl + 8) * CLDR + col) =
                __floats2half2_rn(acc[mt][nt][2], acc[mt][nt][3]);
        }
    }
    __syncthreads();
    constexpr int CH8 = BN / 8;
    #pragma unroll
    for (int j = 0; j < (BM * CH8) / 256; j++) {
        int idx = tid + j * 256;
        int r = idx / CH8, c8 = idx % CH8;
        int grow = row0 + r;
        if (grow < M)
            *(uint4*)(C + (size_t)grow * SC + c8 * 8) = *(uint4*)(Cs + r * CLDR + c8 * 8);
    }
}

// ---------------- flat fp16 GEMM (K=128), node-chunk version -----------------
template<int BN, int SC>
__global__ __launch_bounds__(256, 2) void k_gemm_flat(const __half* __restrict__ A,
                                                      const __half* __restrict__ WT,
                                                      __half* __restrict__ C,
                                                      int base, int M) {
    constexpr int KT = 128, BM = 128;
    constexpr int WTN = BN / 4;
    constexpr int NTL = WTN / 8;
    constexpr int LDR = KT + 8;             // 136 halves = 272B rows, conflict-free
    constexpr int WCH = BN * 16 / 256;

    extern __shared__ __half smem[];
    __half* As = smem;
    __half* Ws = smem + BM * LDR;

    const int tid = threadIdx.x;
    const int wid = tid >> 5;
    const int lane = tid & 31;
    const int g = lane >> 2;
    const int t = lane & 3;
    const int warp_m = wid >> 2;
    const int warp_n = wid & 3;
    const int row0 = base + blockIdx.x * BM;

    const uint32_t sA = (uint32_t)__cvta_generic_to_shared(As);
    const uint32_t sW = (uint32_t)__cvta_generic_to_shared(Ws);

    #pragma unroll
    for (int j = 0; j < 8; j++) {
        int idx = tid + j * 256;
        int r = idx >> 4, ch = idx & 15;
        int grow = row0 + r;
        cp_async16(sA + (uint32_t)((r * LDR + ch * 8) * 2),
                   A + (size_t)grow * KT + ch * 8, grow < M ? 16 : 0);
    }
    #pragma unroll
    for (int j = 0; j < WCH; j++) {
        int idx = tid + j * 256;
        int r = idx >> 4, ch = idx & 15;
        cp_async16(sW + (uint32_t)((r * LDR + ch * 8) * 2),
                   WT + (size_t)r * KT + ch * 8, 16);
    }
    cp_commit();

    float acc[4][NTL][4];
    #pragma unroll
    for (int i = 0; i < 4; i++)
        #pragma unroll
        for (int j = 0; j < NTL; j++)
            #pragma unroll
            for (int r = 0; r < 4; r++) acc[i][j][r] = 0.f;

    cp_wait<0>();
    __syncthreads();

    #pragma unroll
    for (int ks = 0; ks < 8; ks++) {
        const int k16 = ks * 16;
        uint32_t bf[NTL][2];
        #pragma unroll
        for (int np = 0; np < NTL / 2; np++) {
            int n0 = warp_n * WTN + np * 16;
            uint32_t ad = sW + (uint32_t)(((n0 + (lane & 7) + ((lane >> 4) & 1) * 8) * LDR +
                          k16 + ((lane >> 3) & 1) * 8) * 2);
            ldsm_x4(bf[2 * np][0], bf[2 * np][1], bf[2 * np + 1][0], bf[2 * np + 1][1], ad);
        }
        #pragma unroll
        for (int mt = 0; mt < 4; mt++) {
            int mb = warp_m * 64 + mt * 16;
            uint32_t ad = sA + (uint32_t)(((mb + (lane & 15)) * LDR + k16 + (lane >> 4) * 8) * 2);
            uint32_t a0, a1, a2, a3;
            ldsm_x4(a0, a1, a2, a3, ad);
            #pragma unroll
            for (int nt = 0; nt < NTL; nt++) {
                asm volatile(
                    "mma.sync.aligned.m16n8k16.row.col.f32.f16.f16.f32 "
                    "{%0,%1,%2,%3}, {%4,%5,%6,%7}, {%8,%9}, {%0,%1,%2,%3};"
                    : "+f"(acc[mt][nt][0]), "+f"(acc[mt][nt][1]),
                      "+f"(acc[mt][nt][2]), "+f"(acc[mt][nt][3])
                    : "r"(a0), "r"(a1), "r"(a2), "r"(a3),
                      "r"(bf[nt][0]), "r"(bf[nt][1]));
            }
        }
    }

    // ---- epilogue: stage C in smem, coalesced STG.128 ----
    __syncthreads();
    constexpr int CLDR = BN + 8;
    __half* Cs = smem;
    #pragma unroll
    for (int mt = 0; mt < 4; mt++) {
        int rl = warp_m * 64 + mt * 16 + g;
        #pragma unroll
        for (int nt = 0; nt < NTL; nt++) {
            int col = warp_n * WTN + nt * 8 + t * 2;
            *(__half2*)(Cs + rl * CLDR + col) =
                __floats2half2_rn(acc[mt][nt][0], acc[mt][nt][1]);
            *(__half2*)(Cs + (rl + 8) * CLDR + col) =
                __floats2half2_rn(acc[mt][nt][2], acc[mt][nt][3]);
        }
    }
    __syncthreads();
    constexpr int CH8 = BN / 8;
    #pragma unroll
    for (int j = 0; j < (BM * CH8) / 256; j++) {
        int idx = tid + j * 256;
        int r = idx / CH8, c8 = idx % CH8;
        int grow = row0 + r;
        if (grow < M)
            *(uint4*)(C + (size_t)grow * SC + c8 * 8) = *(uint4*)(Cs + r * CLDR + c8 * 8);
    }
}

// ---------------- aggregation (C=128): warp per node, node-chunk version -----
__global__ __launch_bounds__(256) void k_agg128(const __half* __restrict__ hin,
                                                const float* __restrict__ b,
                                                __half* __restrict__ out,
                                                int base, int cnt) {
    int w = (blockIdx.x * blockDim.x + threadIdx.x) >> 5;
    int lane = threadIdx.x & 31;
    if (w >= cnt) return;
    const int node = base + w;
    const uint2* __restrict__ h2 = (const uint2*)hin;
    int e = g_rowptr[node];
    const int e1 = g_rowptr[node + 1];

    float4 acc = make_float4(0.f, 0.f, 0.f, 0.f);

    for (; e + 8 <= e1; e += 8) {
        uint2 p[8]; uint2 v[8];
        #pragma unroll
        for (int j = 0; j < 8; j++) p[j] = __ldg(g_epk + e + j);
        #pragma unroll
        for (int j = 0; j < 8; j++) v[j] = __ldg(h2 + p[j].x * 32 + lane);
        #pragma unroll
        for (int j = 0; j < 8; j++) {
            float wgt = __uint_as_float(p[j].y);
            float2 f0 = __half22float2(*(__half2*)&v[j].x);
            float2 f1 = __half22float2(*(__half2*)&v[j].y);
            acc.x += wgt * f0.x; acc.y += wgt * f0.y;
            acc.z += wgt * f1.x; acc.w += wgt * f1.y;
        }
    }
    for (; e < e1; e++) {
        uint2 p = __ldg(g_epk + e);
        float wgt = __uint_as_float(p.y);
        uint2 v0 = __ldg(h2 + p.x * 32 + lane);
        float2 f0 = __half22float2(*(__half2*)&v0.x);
        float2 f1 = __half22float2(*(__half2*)&v0.y);
        acc.x += wgt * f0.x; acc.y += wgt * f0.y;
        acc.z += wgt * f1.x; acc.w += wgt * f1.y;
    }

    float di = g_dinv[node];
    float sl = di * di;
    uint2 vr = __ldg(h2 + node * 32 + lane);
    float2 vi0 = __half22float2(*(__half2*)&vr.x);
    float2 vi1 = __half22float2(*(__half2*)&vr.y);
    float4 vb = __ldg((const float4*)b + lane);
    __half2 o0 = __floats2half2_rn(fmaxf(acc.x + sl * vi0.x + vb.x, 0.f),
                                   fmaxf(acc.y + sl * vi0.y + vb.y, 0.f));
    __half2 o1 = __floats2half2_rn(fmaxf(acc.z + sl * vi1.x + vb.z, 0.f),
                                   fmaxf(acc.w + sl * vi1.y + vb.w, 0.f));
    uint2 o;
    o.x = *(uint32_t*)&o0;
    o.y = *(uint32_t*)&o1;
    ((uint2*)out)[node * 32 + lane] = o;
}

// ---------------- final aggregation (C=50, half input, no relu) --------------
__global__ __launch_bounds__(256) void k_agg_fin(const __half* __restrict__ h,
                                                 const float* __restrict__ b,
                                                 float* __restrict__ out, int n) {
    int warp = (blockIdx.x * blockDim.x + threadIdx.x) >> 5;
    int lane = threadIdx.x & 31;
    if (warp >= n) return;
    const int i = warp;
    int e = g_rowptr[i];
    const int e1 = g_rowptr[i + 1];
    const int f0 = lane;
    const int f1 = lane + 32;

    float a0 = 0.f, a1 = 0.f;
    for (; e + 4 <= e1; e += 4) {
        uint2 p0 = __ldg(g_epk + e),     p1 = __ldg(g_epk + e + 1);
        uint2 p2 = __ldg(g_epk + e + 2), p3 = __ldg(g_epk + e + 3);
        float n0 = __uint_as_float(p0.y), n1 = __uint_as_float(p1.y);
        float n2 = __uint_as_float(p2.y), n3 = __uint_as_float(p3.y);
        const __half* q0 = h + (size_t)p0.x * 64;
        const __half* q1 = h + (size_t)p1.x * 64;
        const __half* q2 = h + (size_t)p2.x * 64;
        const __half* q3 = h + (size_t)p3.x * 64;
        a0 += n0 * __half2float(__ldg(q0 + f0));
        a0 += n1 * __half2float(__ldg(q1 + f0));
        a0 += n2 * __half2float(__ldg(q2 + f0));
        a0 += n3 * __half2float(__ldg(q3 + f0));
        if (f1 < 50) {
            a1 += n0 * __half2float(__ldg(q0 + f1));
            a1 += n1 * __half2float(__ldg(q1 + f1));
            a1 += n2 * __half2float(__ldg(q2 + f1));
            a1 += n3 * __half2float(__ldg(q3 + f1));
        }
    }
    for (; e < e1; e++) {
        uint2 p = __ldg(g_epk + e);
        float n0 = __uint_as_float(p.y);
        const __half* q0 = h + (size_t)p.x * 64;
        a0 += n0 * __half2float(__ldg(q0 + f0));
        if (f1 < 50) a1 += n0 * __half2float(__ldg(q0 + f1));
    }

    float di = g_dinv[i];
    float sl = di * di;
    const __half* hi = h + (size_t)i * 64;
    out[(size_t)i * 50 + f0] = a0 + sl * __half2float(__ldg(hi + f0)) + __ldg(b + f0);
    if (f1 < 50)
        out[(size_t)i * 50 + f1] = a1 + sl * __half2float(__ldg(hi + f1)) + __ldg(b + f1);
}

// ---------------- launch ----------------
extern "C" void kernel_launch(void* const* d_in, const int* in_sizes, int n_in,
                              void* d_out, int out_size) {
    const float* x  = (const float*)d_in[0];
    const void*  ei = d_in[1];
    const float* W1 = (const float*)d_in[2];  const float* b1 = (const float*)d_in[3];
    const float* W2 = (const float*)d_in[4];  const float* b2 = (const float*)d_in[5];
    const float* W3 = (const float*)d_in[6];  const float* b3 = (const float*)d_in[7];
    const float* W4 = (const float*)d_in[8];  const float* b4 = (const float*)d_in[9];
    const float* W5 = (const float*)d_in[10]; const float* b5 = (const float*)d_in[11];

    const int N = in_sizes[0] / 384;
    const int E = in_sizes[1] / 2;

    __half *hA, *hB, *y, *wt1, *wt2, *wt3, *wt4, *wt5;
    cudaGetSymbolAddress((void**)&hA, g_hA);
    cudaGetSymbolAddress((void**)&hB, g_hB);
    cudaGetSymbolAddress((void**)&y, g_y);
    cudaGetSymbolAddress((void**)&wt1, g_wt1);
    cudaGetSymbolAddress((void**)&wt2, g_wt2);
    cudaGetSymbolAddress((void**)&wt3, g_wt3);
    cudaGetSymbolAddress((void**)&wt4, g_wt4);
    cudaGetSymbolAddress((void**)&wt5, g_wt5);

    const int T = 256;
    const int gN = (N + T - 1) / T;
    const int gE2 = (E / 2 + T) / T;
    const int nb = (N + 1023) / 1024;
    const int gm = (N + 127) / 128;
    const int ga = (N + 7) / 8;

    const int smemCVT  = 2 * (128 + 128) * 40 * 2;  // 40960
    const int smemF128 = (128 + 128) * 136 * 2;     // 69632
    const int smemF64  = (128 + 64) * 136 * 2;      // 52224
    cudaFuncSetAttribute(k_gemm_cvt<384, 128, 128>,
                         cudaFuncAttributeMaxDynamicSharedMemorySize, smemCVT);
    cudaFuncSetAttribute(k_gemm_flat<128, 128>,
                         cudaFuncAttributeMaxDynamicSharedMemorySize, smemF128);
    cudaFuncSetAttribute(k_gemm_flat<64, 64>,
                         cudaFuncAttributeMaxDynamicSharedMemorySize, smemF64);

    // lazily-created side stream + event pool (host handles only)
    static cudaStream_t s2 = nullptr;
    static cudaEvent_t evs[32];
    if (s2 == nullptr) {
        cudaStreamCreateWithFlags(&s2, cudaStreamNonBlocking);
        for (int i = 0; i < 32; i++)
            cudaEventCreateWithFlags(&evs[i], cudaEventDisableTiming);
    }
    int ec = 0;

    // ---- fork: CSR build (+ wt2-5 transpose) on s2, GEMM1 path on main ----
    {
        cudaEvent_t ef = evs[ec++ & 31];
        cudaEventRecord(ef, 0);
        cudaStreamWaitEvent(s2, ef, 0);
    }
    k_init<<<gN, T, 0, s2>>>(ei, E, (long long)N, N);
    k_hist<<<gE2, T, 0, s2>>>(ei, E);
    k_scan1<<<nb, 1024, 0, s2>>>(N);
    k_scan2<<<1, 256, 0, s2>>>(nb, N);
    k_scan3<<<gN, T, 0, s2>>>(N);
    k_scatter<<<gE2, T, 0, s2>>>(ei, E);
    k_wtrans_rest<<<(57344 + 255) / 256, T, 0, s2>>>(W2, W3, W4, W5);
    {
        cudaEvent_t ej = evs[ec++ & 31];
        cudaEventRecord(ej, s2);
        k_wtrans1<<<(49152 + 255) / 256, T>>>(W1);
        k_gemm_cvt<384, 128, 128><<<gm, T, smemCVT>>>(x, wt1, hA, N);
        cudaStreamWaitEvent(0, ej, 0);
    }

    // ---- pipelined layers: agg chunks on main, next-layer GEMM chunks on s2.
    // GEMM output alternates hA/hB so concurrent writes never touch the buffer
    // the aggregation is still gathering from.
    const int NCH = 4;
    const int chunk = (((N + NCH - 1) / NCH) + 127) & ~127;

    auto pipe128 = [&](const __half* hin, const float* bias, const __half* wt,
                       __half* hout) {
        for (int c = 0; c < NCH; c++) {
            int base = c * chunk;
            if (base >= N) break;
            int cnt = (N - base < chunk) ? (N - base) : chunk;
            k_agg128<<<(cnt + 7) / 8, T>>>(hin, bias, y, base, cnt);
            cudaEvent_t ea = evs[ec++ & 31];
            cudaEventRecord(ea, 0);
            cudaStreamWaitEvent(s2, ea, 0);
            k_gemm_flat<128, 128><<<(cnt + 127) / 128, T, smemF128, s2>>>(y, wt, hout, base, N);
        }
        cudaEvent_t el = evs[ec++ & 31];
        cudaEventRecord(el, s2);
        cudaStreamWaitEvent(0, el, 0);
    };

    pipe128(hA, b1, wt2, hB);   // layer1 agg reads hA; layer2 GEMM writes hB
    pipe128(hB, b2, wt3, hA);   // layer2 agg reads hB; layer3 GEMM writes hA
    pipe128(hA, b3, wt4, hB);   // layer3 agg reads hA; layer4 GEMM writes hB
    // layer 4 agg (reads hB) + layer 5 GEMM (BN=64, writes hA)
    for (int c = 0; c < NCH; c++) {
        int base = c * chunk;
        if (base >= N) break;
        int cnt = (N - base < chunk) ? (N - base) : chunk;
        k_agg128<<<(cnt + 7) / 8, T>>>(hB, b4, y, base, cnt);
        cudaEvent_t ea = evs[ec++ & 31];
        cudaEventRecord(ea, 0);
        cudaStreamWaitEvent(s2, ea, 0);
        k_gemm_flat<64, 64><<<(cnt + 127) / 128, T, smemF64, s2>>>(y, wt5, hA, base, N);
    }
    {
        cudaEvent_t el = evs[ec++ & 31];
        cudaEventRecord(el, s2);
        cudaStreamWaitEvent(0, el, 0);
    }

    // final aggregation: hA (stride 64) -> d_out (stride 50)
    k_agg_fin<<<ga, T>>>(hA, b5, (float*)d_out, N);
}